// round 2
// baseline (speedup 1.0000x reference)
#include <cuda_runtime.h>
#include <math.h>

// Problem constants
#define BB 32
#define LL 1024
#define EMB 128
#define HH 384
#define NLAYER 4
#define NVOCAB 100
#define G4 (4*HH)          // 1536
#define MM (BB*LL)         // 32768
#define CTXIN 300
#define HB (HH*BB)         // 12288

// ---------------- static scratch (no allocations allowed) ----------------
__device__ float g_x0[MM * 2 * EMB];            // layer-0 input [M,256]
__device__ float g_seqA[MM * HH];
__device__ float g_seqB[MM * HH];
__device__ float g_pre[(size_t)MM * G4];        // input projection [m=b*L+t][1536]
__device__ float g_preT[(size_t)MM * G4];       // transposed [t][row][b]
__device__ float g_keys[MM * HH];               // keys, later reused as ctx_vec
__device__ float g_scores[(size_t)BB * LL * LL];// attention scores / attn (in place)
__device__ float g_cat[MM * 2 * HH];            // [out | ctx]
__device__ float g_comb[MM * HH];
__device__ float g_hT[2 * HB];                  // double-buffered h, [k][b] layout
__device__ unsigned g_barCount;                 // grid barrier arrival counter

// ---------------- generic SGEMM: C = act(scale * A @ W^T + b1 + b2) -------
// A[M,K] row-major (lda), W[N,K] row-major (ldw). 128x128x8 tiles, 8x8/thread.
__global__ __launch_bounds__(256)
void gemm_awt(const float* __restrict__ A, int lda,
              const float* __restrict__ W, int ldw,
              const float* __restrict__ b1, const float* __restrict__ b2,
              float* __restrict__ C, int ldc,
              int M, int N, int K,
              float scale, int act, int causal,
              size_t sA, size_t sW, size_t sC)
{
    int m0 = blockIdx.y * 128;
    int n0 = blockIdx.x * 128;
    if (causal && n0 > m0 + 127) return;
    A += (size_t)blockIdx.z * sA;
    W += (size_t)blockIdx.z * sW;
    C += (size_t)blockIdx.z * sC;

    __shared__ __align__(16) float As[8][128];
    __shared__ __align__(16) float Ws[8][128];

    int tid = threadIdx.x;
    int tx = tid & 15, ty = tid >> 4;
    int lr = tid >> 1, lq = tid & 1;

    float acc[8][8];
#pragma unroll
    for (int i = 0; i < 8; i++)
#pragma unroll
        for (int j = 0; j < 8; j++) acc[i][j] = 0.f;

    for (int k0 = 0; k0 < K; k0 += 8) {
        float4 av, wv;
        if (k0 + 8 <= K) {
            av = *(const float4*)(A + (size_t)(m0 + lr) * lda + k0 + lq * 4);
        } else {
            const float* ap = A + (size_t)(m0 + lr) * lda;
            int kb = k0 + lq * 4;
            float t0 = 0, t1 = 0, t2 = 0, t3 = 0;
            if (kb + 0 < K) t0 = ap[kb + 0];
            if (kb + 1 < K) t1 = ap[kb + 1];
            if (kb + 2 < K) t2 = ap[kb + 2];
            if (kb + 3 < K) t3 = ap[kb + 3];
            av = make_float4(t0, t1, t2, t3);
        }
        int wr = n0 + lr;
        if (wr < N) {
            if (k0 + 8 <= K) {
                wv = *(const float4*)(W + (size_t)wr * ldw + k0 + lq * 4);
            } else {
                const float* wp = W + (size_t)wr * ldw;
                int kb = k0 + lq * 4;
                float t0 = 0, t1 = 0, t2 = 0, t3 = 0;
                if (kb + 0 < K) t0 = wp[kb + 0];
                if (kb + 1 < K) t1 = wp[kb + 1];
                if (kb + 2 < K) t2 = wp[kb + 2];
                if (kb + 3 < K) t3 = wp[kb + 3];
                wv = make_float4(t0, t1, t2, t3);
            }
        } else {
            wv = make_float4(0, 0, 0, 0);
        }
        __syncthreads();
        As[lq * 4 + 0][lr] = av.x; As[lq * 4 + 1][lr] = av.y;
        As[lq * 4 + 2][lr] = av.z; As[lq * 4 + 3][lr] = av.w;
        Ws[lq * 4 + 0][lr] = wv.x; Ws[lq * 4 + 1][lr] = wv.y;
        Ws[lq * 4 + 2][lr] = wv.z; Ws[lq * 4 + 3][lr] = wv.w;
        __syncthreads();
#pragma unroll
        for (int kk = 0; kk < 8; kk++) {
            float a[8], w[8];
            *(float4*)(a)     = *(const float4*)(&As[kk][ty * 8]);
            *(float4*)(a + 4) = *(const float4*)(&As[kk][ty * 8 + 4]);
            *(float4*)(w)     = *(const float4*)(&Ws[kk][tx * 8]);
            *(float4*)(w + 4) = *(const float4*)(&Ws[kk][tx * 8 + 4]);
#pragma unroll
            for (int i = 0; i < 8; i++)
#pragma unroll
                for (int j = 0; j < 8; j++) acc[i][j] += a[i] * w[j];
        }
    }
#pragma unroll
    for (int i = 0; i < 8; i++) {
        int m = m0 + ty * 8 + i;
#pragma unroll
        for (int j = 0; j < 8; j++) {
            int n = n0 + tx * 8 + j;
            if (n < N) {
                float v = acc[i][j] * scale;
                if (b1) v += b1[n];
                if (b2) v += b2[n];
                if (act) v = tanhf(v);
                C[(size_t)m * ldc + n] = v;
            }
        }
    }
}

// ---------------- C = A @ B (B not transposed), batched, causal-K --------
__global__ __launch_bounds__(256)
void gemm_ab(const float* __restrict__ A, int lda,
             const float* __restrict__ B, int ldb,
             float* __restrict__ C, int ldc,
             int M, int N, int K, int causalK,
             size_t sA, size_t sB, size_t sC)
{
    int m0 = blockIdx.y * 128;
    int n0 = blockIdx.x * 128;
    A += (size_t)blockIdx.z * sA;
    B += (size_t)blockIdx.z * sB;
    C += (size_t)blockIdx.z * sC;

    __shared__ __align__(16) float As[8][128];
    __shared__ __align__(16) float Bs[8][128];

    int tid = threadIdx.x;
    int tx = tid & 15, ty = tid >> 4;
    int lr = tid >> 1, lq = tid & 1;

    float acc[8][8];
#pragma unroll
    for (int i = 0; i < 8; i++)
#pragma unroll
        for (int j = 0; j < 8; j++) acc[i][j] = 0.f;

    int kEnd = causalK ? min(K, m0 + 128) : K;
    for (int k0 = 0; k0 < kEnd; k0 += 8) {
        float4 av = *(const float4*)(A + (size_t)(m0 + lr) * lda + k0 + lq * 4);
        float bv[4];
#pragma unroll
        for (int i = 0; i < 4; i++) {
            int e = tid + i * 256;
            int kk = e >> 7, n = e & 127;
            bv[i] = B[(size_t)(k0 + kk) * ldb + n0 + n];
        }
        __syncthreads();
        As[lq * 4 + 0][lr] = av.x; As[lq * 4 + 1][lr] = av.y;
        As[lq * 4 + 2][lr] = av.z; As[lq * 4 + 3][lr] = av.w;
#pragma unroll
        for (int i = 0; i < 4; i++) {
            int e = tid + i * 256;
            Bs[e >> 7][e & 127] = bv[i];
        }
        __syncthreads();
#pragma unroll
        for (int kk = 0; kk < 8; kk++) {
            float a[8], w[8];
            *(float4*)(a)     = *(const float4*)(&As[kk][ty * 8]);
            *(float4*)(a + 4) = *(const float4*)(&As[kk][ty * 8 + 4]);
            *(float4*)(w)     = *(const float4*)(&Bs[kk][tx * 8]);
            *(float4*)(w + 4) = *(const float4*)(&Bs[kk][tx * 8 + 4]);
#pragma unroll
            for (int i = 0; i < 8; i++)
#pragma unroll
                for (int j = 0; j < 8; j++) acc[i][j] += a[i] * w[j];
        }
    }
#pragma unroll
    for (int i = 0; i < 8; i++) {
        int m = m0 + ty * 8 + i;
#pragma unroll
        for (int j = 0; j < 8; j++) {
            int n = n0 + tx * 8 + j;
            if (n < N) C[(size_t)m * ldc + n] = acc[i][j];
        }
    }
}

// ---------------- embedding gather ----------------
__global__ void embed_kernel(const int* __restrict__ x, const float* __restrict__ emb,
                             float* __restrict__ X0)
{
    int i = blockIdx.x * 256 + threadIdx.x;
    if (i >= MM * EMB) return;
    int m = i >> 7, e = i & 127;
    X0[(size_t)m * 256 + e] = emb[(size_t)x[m] * EMB + e];
}

// ---------------- pre transpose: [b*L+t][row] -> [t][row][b] ------------
__global__ __launch_bounds__(1024)
void transpose_pre(const float* __restrict__ in, float* __restrict__ out)
{
    __shared__ float tile[32][33];
    int t = blockIdx.x;            // 0..1023
    int r0 = blockIdx.y * 32;      // row base, 0..1535
    int x = threadIdx.x, y = threadIdx.y;
    // read: b=y, row=r0+x (coalesced over x)
    tile[y][x] = in[((size_t)y * LL + t) * G4 + r0 + x];
    __syncthreads();
    // write: row=r0+y, b=x (coalesced over x)
    out[((size_t)t * G4 + r0 + y) * BB + x] = tile[x][y];
}

// ---------------- persistent LSTM layer ----------------
// grid 128 CTAs x 96 threads (3 hidden dims x 32 batch per CTA), all co-resident.
// Software grid barrier per timestep; weights stay L1-hot; c-state in registers.
__global__ __launch_bounds__(96, 1)
void lstm_layer(const float* __restrict__ preT,  // [t][row][b]
                const float* __restrict__ Whh,   // [1536,384]
                const float* __restrict__ h0,    // [B,H]
                const float* __restrict__ c0,    // [B,H]
                float* __restrict__ Y,           // [B,L,H]
                float* __restrict__ hT,          // [2][H][B]
                float* __restrict__ outh,        // [B,H] or null
                float* __restrict__ outc,
                int writeState)
{
    __shared__ float hs[HB];   // 48 KB, [k][b]
    const int tid = threadIdx.x;
    const int b = tid & 31;
    const int jl = tid >> 5;
    const int jg = blockIdx.x * 3 + jl;

    float h = h0[b * HH + jg];
    float c = c0[b * HH + jg];
    hT[jg * BB + b] = h;       // buffer 0

    const float* w0 = Whh + (size_t)jg * HH;
    const float* w1 = w0 + (size_t)HH * HH;
    const float* w2 = w1 + (size_t)HH * HH;
    const float* w3 = w2 + (size_t)HH * HH;

    for (int t = 0; t < LL; t++) {
        // ---- grid barrier #(t+1): previous h writes visible chip-wide ----
        __threadfence();
        __syncthreads();
        if (tid == 0) {
            atomicAdd(&g_barCount, 1u);
            unsigned tgt = 128u * (unsigned)(t + 1);
            while (*((volatile unsigned*)&g_barCount) < tgt) {}
        }
        __syncthreads();

        // ---- stage h(t) into smem (bypass L1 with .cv) ----
        const float4* src = (const float4*)(hT + (t & 1) * HB);
        float4* dst4 = (float4*)hs;
#pragma unroll
        for (int i = 0; i < 32; i++)
            dst4[tid + i * 96] = __ldcv(src + tid + i * 96);
        __syncthreads();

        // ---- gates: pre + h @ Whh^T ----
        size_t base = ((size_t)t * G4) * BB + b;
        float acc0 = preT[base + (size_t)jg * BB];
        float acc1 = preT[base + (size_t)(HH + jg) * BB];
        float acc2 = preT[base + (size_t)(2 * HH + jg) * BB];
        float acc3 = preT[base + (size_t)(3 * HH + jg) * BB];

#pragma unroll 8
        for (int k = 0; k < HH; k += 4) {
            float4 a0 = *(const float4*)(w0 + k);
            float4 a1 = *(const float4*)(w1 + k);
            float4 a2 = *(const float4*)(w2 + k);
            float4 a3 = *(const float4*)(w3 + k);
            float h0v = hs[(k + 0) * BB + b];
            float h1v = hs[(k + 1) * BB + b];
            float h2v = hs[(k + 2) * BB + b];
            float h3v = hs[(k + 3) * BB + b];
            acc0 += a0.x * h0v + a0.y * h1v + a0.z * h2v + a0.w * h3v;
            acc1 += a1.x * h0v + a1.y * h1v + a1.z * h2v + a1.w * h3v;
            acc2 += a2.x * h0v + a2.y * h1v + a2.z * h2v + a2.w * h3v;
            acc3 += a3.x * h0v + a3.y * h1v + a3.z * h2v + a3.w * h3v;
        }

        float ig = 1.f / (1.f + expf(-acc0));
        float fg = 1.f / (1.f + expf(-acc1));
        float gg = tanhf(acc2);
        float og = 1.f / (1.f + expf(-acc3));
        c = fg * c + ig * gg;
        h = og * tanhf(c);

        hT[((t + 1) & 1) * HB + jg * BB + b] = h;
        Y[((size_t)b * LL + t) * HH + jg] = h;
    }

    if (writeState) {
        outh[b * HH + jg] = h;
        outc[b * HH + jg] = c;
    }
}

// ---------------- causal softmax (in place, zero-fills masked region) ----
__global__ __launch_bounds__(256)
void softmax_causal(float* __restrict__ S)
{
    int bq = blockIdx.x;
    int b = bq >> 10, q = bq & 1023;
    float* row = S + ((size_t)b * LL + q) * LL;
    int len = q + 1;
    int tid = threadIdx.x;
    __shared__ float red[256];

    float mx = -1e30f;
    for (int k = tid; k < len; k += 256) mx = fmaxf(mx, row[k]);
    red[tid] = mx; __syncthreads();
    for (int s = 128; s > 0; s >>= 1) {
        if (tid < s) red[tid] = fmaxf(red[tid], red[tid + s]);
        __syncthreads();
    }
    mx = red[0]; __syncthreads();

    float sum = 0.f;
    for (int k = tid; k < len; k += 256) sum += expf(row[k] - mx);
    red[tid] = sum; __syncthreads();
    for (int s = 128; s > 0; s >>= 1) {
        if (tid < s) red[tid] += red[tid + s];
        __syncthreads();
    }
    sum = red[0]; __syncthreads();

    float inv = 1.f / sum;
    for (int k = tid; k < LL; k += 256)
        row[k] = (k < len) ? expf(row[k] - mx) * inv : 0.f;
}

// ---------------- concat [out | ctx] ----------------
__global__ void concat_kernel(const float* __restrict__ Yout, const float* __restrict__ ctx,
                              float* __restrict__ cat)
{
    int i = blockIdx.x * 256 + threadIdx.x;
    if (i >= MM * 2 * HH) return;
    int m = i / (2 * HH), j = i % (2 * HH);
    cat[i] = (j < HH) ? Yout[(size_t)m * HH + j] : ctx[(size_t)m * HH + j - HH];
}

// ---------------- host ----------------
extern "C" void kernel_launch(void* const* d_in, const int* in_sizes, int n_in,
                              void* d_out, int out_size)
{
    const int*   x       = (const int*)d_in[0];
    const float* context = (const float*)d_in[1];
    const float* h_in    = (const float*)d_in[2];
    const float* c_in    = (const float*)d_in[3];
    const float* emb     = (const float*)d_in[4];
    const float* ctx_W   = (const float*)d_in[5];
    const float* ctx_b   = (const float*)d_in[6];
    const float* Wih0    = (const float*)d_in[7];
    const float* WihR    = (const float*)d_in[8];
    const float* Whh     = (const float*)d_in[9];
    const float* bih     = (const float*)d_in[10];
    const float* bhh     = (const float*)d_in[11];
    const float* Wa      = (const float*)d_in[12];
    const float* comb_W  = (const float*)d_in[13];
    const float* comb_b  = (const float*)d_in[14];
    const float* fc_W    = (const float*)d_in[15];
    const float* fc_b    = (const float*)d_in[16];
    float* out = (float*)d_out;

    float *x0, *seqA, *seqB, *pre, *preT, *keys, *scores, *cat, *comb, *hT;
    unsigned* barCount;
    cudaGetSymbolAddress((void**)&x0,       g_x0);
    cudaGetSymbolAddress((void**)&seqA,     g_seqA);
    cudaGetSymbolAddress((void**)&seqB,     g_seqB);
    cudaGetSymbolAddress((void**)&pre,      g_pre);
    cudaGetSymbolAddress((void**)&preT,     g_preT);
    cudaGetSymbolAddress((void**)&keys,     g_keys);
    cudaGetSymbolAddress((void**)&scores,   g_scores);
    cudaGetSymbolAddress((void**)&cat,      g_cat);
    cudaGetSymbolAddress((void**)&comb,     g_comb);
    cudaGetSymbolAddress((void**)&hT,       g_hT);
    cudaGetSymbolAddress((void**)&barCount, g_barCount);

    const int logitsN = MM * NVOCAB;             // 3,276,800
    const bool wantState = (out_size >= logitsN + 2 * NLAYER * BB * HH);

    // 1) embedding + context projection -> x0 [M,256]
    embed_kernel<<<(MM * EMB + 255) / 256, 256>>>(x, emb, x0);
    gemm_awt<<<dim3(1, 256, 1), 256>>>(context, CTXIN, ctx_W, CTXIN, ctx_b, nullptr,
                                       x0 + EMB, 2 * EMB, MM, EMB, CTXIN,
                                       1.f, 0, 0, 0, 0, 0);

    // 2) LSTM layers
    for (int l = 0; l < NLAYER; l++) {
        const float* X   = (l == 0) ? x0 : ((l == 1) ? seqA : ((l == 2) ? seqB : seqA));
        int          Kl  = (l == 0) ? 2 * EMB : HH;
        float*       Y   = (l % 2 == 0) ? seqA : seqB;
        const float* Wih = (l == 0) ? Wih0 : (WihR + (size_t)(l - 1) * G4 * HH);

        // input projection + biases: pre[m][row]
        gemm_awt<<<dim3(G4 / 128, MM / 128, 1), 256>>>(X, Kl, Wih, Kl,
                                                       bih + l * G4, bhh + l * G4,
                                                       pre, G4, MM, G4, Kl,
                                                       1.f, 0, 0, 0, 0, 0);
        // transpose to [t][row][b] for coalesced recurrence reads
        transpose_pre<<<dim3(LL, G4 / 32), dim3(32, 32)>>>(pre, preT);

        // recurrence (persistent, software grid barrier)
        cudaMemsetAsync(barCount, 0, sizeof(unsigned));
        const float* Whh_l = Whh + (size_t)l * G4 * HH;
        float* outh = wantState ? (out + logitsN + l * BB * HH) : nullptr;
        float* outc = wantState ? (out + logitsN + NLAYER * BB * HH + l * BB * HH) : nullptr;
        lstm_layer<<<128, 96>>>(preT, Whh_l,
                                h_in + l * BB * HH, c_in + l * BB * HH,
                                Y, hT, outh, outc, wantState ? 1 : 0);
    }
    float* Y3 = seqB;  // layer-3 output

    // 3) attention
    gemm_awt<<<dim3(HH / 128, MM / 128, 1), 256>>>(Y3, HH, Wa, HH, nullptr, nullptr,
                                                   keys, HH, MM, HH, HH,
                                                   1.f, 0, 0, 0, 0, 0);
    float invs = 1.f / sqrtf((float)HH);
    gemm_awt<<<dim3(8, 8, 32), 256>>>(Y3, HH, keys, HH, nullptr, nullptr,
                                      scores, LL, LL, LL, HH,
                                      invs, 0, 1,
                                      (size_t)LL * HH, (size_t)LL * HH, (size_t)LL * LL);
    softmax_causal<<<BB * LL, 256>>>(scores);
    // ctx = attn @ out  (reuse keys buffer for ctx)
    gemm_ab<<<dim3(HH / 128, 8, 32), 256>>>(scores, LL, Y3, HH, keys, HH,
                                            LL, HH, LL, 1,
                                            (size_t)LL * LL, (size_t)LL * HH, (size_t)LL * HH);

    // 4) combine + output head
    concat_kernel<<<(MM * 2 * HH + 255) / 256, 256>>>(Y3, keys, cat);
    gemm_awt<<<dim3(HH / 128, MM / 128, 1), 256>>>(cat, 2 * HH, comb_W, 2 * HH,
                                                   comb_b, nullptr, comb, HH,
                                                   MM, HH, 2 * HH,
                                                   1.f, 1, 0, 0, 0, 0);
    gemm_awt<<<dim3(1, MM / 128, 1), 256>>>(comb, HH, fc_W, HH, fc_b, nullptr,
                                            out, NVOCAB, MM, NVOCAB, HH,
                                            1.f, 0, 0, 0, 0, 0);
}

// round 5
// speedup vs baseline: 1.0139x; 1.0139x over previous
#include <cuda_runtime.h>
#include <math.h>

// Problem constants
#define BB 32
#define LL 1024
#define EMB 128
#define HH 384
#define NLAYER 4
#define NVOCAB 100
#define G4 (4*HH)          // 1536
#define MM (BB*LL)         // 32768
#define CTXIN 300
#define HB (HH*BB)         // 12288

// ---------------- static scratch (no allocations allowed) ----------------
__device__ float g_x0[MM * 2 * EMB];            // layer-0 input [M,256]
__device__ float g_seqA[MM * HH];
__device__ float g_seqB[MM * HH];
__device__ float g_pre[(size_t)MM * G4];        // input projection [m=b*L+t][1536]
__device__ float g_preT[(size_t)MM * G4];       // transposed [t][row][b]
__device__ float g_keys[MM * HH];               // keys, later reused as ctx_vec
__device__ float g_scores[(size_t)BB * LL * LL];// attention scores / attn (in place)
__device__ float g_cat[MM * 2 * HH];            // [out | ctx]
__device__ float g_comb[MM * HH];
__device__ float g_hT[2 * HB];                  // double-buffered h, [k][b] layout
__device__ unsigned g_barCount;                 // grid barrier arrival counter

// ---------------- tf32 helpers ----------------
__device__ __forceinline__ unsigned f2tf(float x) {
    unsigned r;
    asm("cvt.rna.tf32.f32 %0, %1;" : "=r"(r) : "f"(x));
    return r;
}

__device__ __forceinline__ void mma8(float* c, const unsigned* a, const unsigned* b) {
    asm volatile(
        "mma.sync.aligned.m16n8k8.row.col.f32.tf32.tf32.f32 "
        "{%0,%1,%2,%3}, {%4,%5,%6,%7}, {%8,%9}, {%0,%1,%2,%3};"
        : "+f"(c[0]), "+f"(c[1]), "+f"(c[2]), "+f"(c[3])
        : "r"(a[0]), "r"(a[1]), "r"(a[2]), "r"(a[3]), "r"(b[0]), "r"(b[1]));
}

// ---------------- tensor-core GEMM (3xTF32, ~fp32 accuracy) ----------------
// C = act(scale * (A @ OP) + b1 + b2)
//   trans=1: OP = W^T, W[N,K] row-major (ldw = K-stride)
//   trans=0: OP = B,   B[K,N] row-major (ldw = N-stride); requires N%128==0
// causal: skip tile if n0 > m0+127.  causalK: truncate K at m0+128.
#define SP 132   // smem row pitch (floats), padded for conflict-free fragment LDS
__global__ __launch_bounds__(256)
void gemm_tc(const float* __restrict__ A, int lda,
             const float* __restrict__ W, int ldw,
             const float* __restrict__ b1, const float* __restrict__ b2,
             float* __restrict__ C, int ldc,
             int M, int N, int K,
             float scale, int act, int causal, int causalK, int trans,
             size_t sA, size_t sW, size_t sC)
{
    int m0 = blockIdx.y * 128;
    int n0 = blockIdx.x * 128;
    if (causal && n0 > m0 + 127) return;
    A += (size_t)blockIdx.z * sA;
    W += (size_t)blockIdx.z * sW;
    C += (size_t)blockIdx.z * sC;
    int Klim = causalK ? min(K, m0 + 128) : K;

    __shared__ float As_hi[16 * SP], As_lo[16 * SP];
    __shared__ float Bs_hi[16 * SP], Bs_lo[16 * SP];

    const int tid = threadIdx.x;
    const int lr = tid >> 1, lq = tid & 1;         // A / W-trans staging
    const int kr = tid >> 4, nc = (tid & 15) * 8;  // B no-trans staging
    const int lane = tid & 31;
    const int g = lane >> 2, tg = lane & 3;
    const int wid = tid >> 5;
    const int mBase = (wid & 3) * 32;
    const int nBase = (wid >> 2) * 64;

    float acc[2][8][4];
#pragma unroll
    for (int mt = 0; mt < 2; mt++)
#pragma unroll
        for (int nt = 0; nt < 8; nt++)
#pragma unroll
            for (int i = 0; i < 4; i++) acc[mt][nt][i] = 0.f;

    float4 a4[2], b4[2];

    // ---- initial prefetch (k0 = 0) ----
#define LOAD_TILE(K0)                                                          \
    {                                                                          \
        int k0_ = (K0);                                                        \
        const float* ap = A + (size_t)(m0 + lr) * lda;                         \
        _Pragma("unroll")                                                      \
        for (int j = 0; j < 2; j++) {                                          \
            int kb = k0_ + lq * 8 + j * 4;                                     \
            float4 v = make_float4(0.f, 0.f, 0.f, 0.f);                        \
            if (kb + 3 < Klim) v = *(const float4*)(ap + kb);                  \
            else {                                                             \
                if (kb + 0 < Klim) v.x = ap[kb + 0];                           \
                if (kb + 1 < Klim) v.y = ap[kb + 1];                           \
                if (kb + 2 < Klim) v.z = ap[kb + 2];                           \
            }                                                                  \
            a4[j] = v;                                                         \
        }                                                                      \
        if (trans) {                                                           \
            int wr = n0 + lr;                                                  \
            const float* wp = W + (size_t)wr * ldw;                            \
            _Pragma("unroll")                                                  \
            for (int j = 0; j < 2; j++) {                                      \
                int kb = k0_ + lq * 8 + j * 4;                                 \
                float4 v = make_float4(0.f, 0.f, 0.f, 0.f);                    \
                if (wr < N) {                                                  \
                    if (kb + 3 < Klim) v = *(const float4*)(wp + kb);          \
                    else {                                                     \
                        if (kb + 0 < Klim) v.x = wp[kb + 0];                   \
                        if (kb + 1 < Klim) v.y = wp[kb + 1];                   \
                        if (kb + 2 < Klim) v.z = wp[kb + 2];                   \
                    }                                                          \
                }                                                              \
                b4[j] = v;                                                     \
            }                                                                  \
        } else {                                                               \
            int kk = k0_ + kr;                                                 \
            _Pragma("unroll")                                                  \
            for (int j = 0; j < 2; j++) {                                      \
                float4 v = make_float4(0.f, 0.f, 0.f, 0.f);                    \
                if (kk < Klim)                                                 \
                    v = *(const float4*)(W + (size_t)kk * ldw + n0 + nc + j * 4);\
                b4[j] = v;                                                     \
            }                                                                  \
        }                                                                      \
    }

    LOAD_TILE(0);

    for (int k0 = 0; k0 < Klim; k0 += 16) {
        // ---- store staged regs to smem (hi/lo split) ----
#pragma unroll
        for (int j = 0; j < 2; j++) {
            const float* pv = &a4[j].x;
            int kb = lq * 8 + j * 4;
#pragma unroll
            for (int i = 0; i < 4; i++) {
                float a = pv[i];
                float hf = __uint_as_float(f2tf(a));
                As_hi[(kb + i) * SP + lr] = hf;
                As_lo[(kb + i) * SP + lr] = __uint_as_float(f2tf(a - hf));
            }
        }
        if (trans) {
#pragma unroll
            for (int j = 0; j < 2; j++) {
                const float* pv = &b4[j].x;
                int kb = lq * 8 + j * 4;
#pragma unroll
                for (int i = 0; i < 4; i++) {
                    float a = pv[i];
                    float hf = __uint_as_float(f2tf(a));
                    Bs_hi[(kb + i) * SP + lr] = hf;
                    Bs_lo[(kb + i) * SP + lr] = __uint_as_float(f2tf(a - hf));
                }
            }
        } else {
#pragma unroll
            for (int j = 0; j < 2; j++) {
                const float* pv = &b4[j].x;
#pragma unroll
                for (int i = 0; i < 4; i++) {
                    float a = pv[i];
                    float hf = __uint_as_float(f2tf(a));
                    Bs_hi[kr * SP + nc + j * 4 + i] = hf;
                    Bs_lo[kr * SP + nc + j * 4 + i] = __uint_as_float(f2tf(a - hf));
                }
            }
        }
        __syncthreads();

        // ---- prefetch next tile ----
        if (k0 + 16 < Klim) LOAD_TILE(k0 + 16);

        // ---- compute on smem ----
#pragma unroll
        for (int kt = 0; kt < 2; kt++) {
            int kr0 = kt * 8 + tg, kr1 = kt * 8 + tg + 4;
            unsigned ah[2][4], al[2][4];
#pragma unroll
            for (int mt = 0; mt < 2; mt++) {
                int m = mBase + mt * 16 + g;
                ah[mt][0] = __float_as_uint(As_hi[kr0 * SP + m]);
                ah[mt][1] = __float_as_uint(As_hi[kr0 * SP + m + 8]);
                ah[mt][2] = __float_as_uint(As_hi[kr1 * SP + m]);
                ah[mt][3] = __float_as_uint(As_hi[kr1 * SP + m + 8]);
                al[mt][0] = __float_as_uint(As_lo[kr0 * SP + m]);
                al[mt][1] = __float_as_uint(As_lo[kr0 * SP + m + 8]);
                al[mt][2] = __float_as_uint(As_lo[kr1 * SP + m]);
                al[mt][3] = __float_as_uint(As_lo[kr1 * SP + m + 8]);
            }
#pragma unroll
            for (int nt = 0; nt < 8; nt++) {
                int n = nBase + nt * 8 + g;
                unsigned bh[2], bl[2];
                bh[0] = __float_as_uint(Bs_hi[kr0 * SP + n]);
                bh[1] = __float_as_uint(Bs_hi[kr1 * SP + n]);
                bl[0] = __float_as_uint(Bs_lo[kr0 * SP + n]);
                bl[1] = __float_as_uint(Bs_lo[kr1 * SP + n]);
#pragma unroll
                for (int mt = 0; mt < 2; mt++) {
                    mma8(acc[mt][nt], ah[mt], bh);
                    mma8(acc[mt][nt], ah[mt], bl);
                    mma8(acc[mt][nt], al[mt], bh);
                }
            }
        }
        __syncthreads();
    }

    // ---- epilogue ----
#pragma unroll
    for (int mt = 0; mt < 2; mt++) {
        int row0 = m0 + mBase + mt * 16 + g;
        int row1 = row0 + 8;
#pragma unroll
        for (int nt = 0; nt < 8; nt++) {
            int col = n0 + nBase + nt * 8 + 2 * tg;
            float bias = 0.f;
            float bias1 = 0.f;
            if (col < N) {
                if (b1) bias += b1[col];
                if (b2) bias += b2[col];
            }
            if (col + 1 < N) {
                if (b1) bias1 += b1[col + 1];
                if (b2) bias1 += b2[col + 1];
            }
            float v0 = acc[mt][nt][0] * scale + bias;
            float v1 = acc[mt][nt][1] * scale + bias1;
            float v2 = acc[mt][nt][2] * scale + bias;
            float v3 = acc[mt][nt][3] * scale + bias1;
            if (act) { v0 = tanhf(v0); v1 = tanhf(v1); v2 = tanhf(v2); v3 = tanhf(v3); }
            if (col + 1 < N) {
                *(float2*)(C + (size_t)row0 * ldc + col) = make_float2(v0, v1);
                *(float2*)(C + (size_t)row1 * ldc + col) = make_float2(v2, v3);
            } else if (col < N) {
                C[(size_t)row0 * ldc + col] = v0;
                C[(size_t)row1 * ldc + col] = v2;
            }
        }
    }
}

// ---------------- embedding gather ----------------
__global__ void embed_kernel(const int* __restrict__ x, const float* __restrict__ emb,
                             float* __restrict__ X0)
{
    int i = blockIdx.x * 256 + threadIdx.x;
    if (i >= MM * EMB) return;
    int m = i >> 7, e = i & 127;
    X0[(size_t)m * 256 + e] = emb[(size_t)x[m] * EMB + e];
}

// ---------------- pre transpose: [b*L+t][row] -> [t][row][b] ------------
__global__ __launch_bounds__(1024)
void transpose_pre(const float* __restrict__ in, float* __restrict__ out)
{
    __shared__ float tile[32][33];
    int t = blockIdx.x;            // 0..1023
    int r0 = blockIdx.y * 32;      // row base, 0..1535
    int x = threadIdx.x, y = threadIdx.y;
    tile[y][x] = in[((size_t)y * LL + t) * G4 + r0 + x];
    __syncthreads();
    out[((size_t)t * G4 + r0 + y) * BB + x] = tile[x][y];
}

// ---------------- persistent LSTM layer ----------------
__global__ __launch_bounds__(96, 1)
void lstm_layer(const float* __restrict__ preT,  // [t][row][b]
                const float* __restrict__ Whh,   // [1536,384]
                const float* __restrict__ h0,    // [B,H]
                const float* __restrict__ c0,    // [B,H]
                float* __restrict__ Y,           // [B,L,H]
                float* __restrict__ hT,          // [2][H][B]
                float* __restrict__ outh,        // [B,H] or null
                float* __restrict__ outc,
                int writeState)
{
    __shared__ float hs[HB];   // 48 KB, [k][b]
    const int tid = threadIdx.x;
    const int b = tid & 31;
    const int jl = tid >> 5;
    const int jg = blockIdx.x * 3 + jl;

    float h = h0[b * HH + jg];
    float c = c0[b * HH + jg];
    hT[jg * BB + b] = h;       // buffer 0

    const float* w0 = Whh + (size_t)jg * HH;
    const float* w1 = w0 + (size_t)HH * HH;
    const float* w2 = w1 + (size_t)HH * HH;
    const float* w3 = w2 + (size_t)HH * HH;

    for (int t = 0; t < LL; t++) {
        __threadfence();
        __syncthreads();
        if (tid == 0) {
            atomicAdd(&g_barCount, 1u);
            unsigned tgt = 128u * (unsigned)(t + 1);
            while (*((volatile unsigned*)&g_barCount) < tgt) {}
        }
        __syncthreads();

        const float4* src = (const float4*)(hT + (t & 1) * HB);
        float4* dst4 = (float4*)hs;
#pragma unroll
        for (int i = 0; i < 32; i++)
            dst4[tid + i * 96] = __ldcv(src + tid + i * 96);
        __syncthreads();

        size_t base = ((size_t)t * G4) * BB + b;
        float acc0 = preT[base + (size_t)jg * BB];
        float acc1 = preT[base + (size_t)(HH + jg) * BB];
        float acc2 = preT[base + (size_t)(2 * HH + jg) * BB];
        float acc3 = preT[base + (size_t)(3 * HH + jg) * BB];

#pragma unroll 8
        for (int k = 0; k < HH; k += 4) {
            float4 a0 = *(const float4*)(w0 + k);
            float4 a1 = *(const float4*)(w1 + k);
            float4 a2 = *(const float4*)(w2 + k);
            float4 a3 = *(const float4*)(w3 + k);
            float h0v = hs[(k + 0) * BB + b];
            float h1v = hs[(k + 1) * BB + b];
            float h2v = hs[(k + 2) * BB + b];
            float h3v = hs[(k + 3) * BB + b];
            acc0 += a0.x * h0v + a0.y * h1v + a0.z * h2v + a0.w * h3v;
            acc1 += a1.x * h0v + a1.y * h1v + a1.z * h2v + a1.w * h3v;
            acc2 += a2.x * h0v + a2.y * h1v + a2.z * h2v + a2.w * h3v;
            acc3 += a3.x * h0v + a3.y * h1v + a3.z * h2v + a3.w * h3v;
        }

        float ig = 1.f / (1.f + expf(-acc0));
        float fg = 1.f / (1.f + expf(-acc1));
        float gg = tanhf(acc2);
        float og = 1.f / (1.f + expf(-acc3));
        c = fg * c + ig * gg;
        h = og * tanhf(c);

        hT[((t + 1) & 1) * HB + jg * BB + b] = h;
        Y[((size_t)b * LL + t) * HH + jg] = h;
    }

    if (writeState) {
        outh[b * HH + jg] = h;
        outc[b * HH + jg] = c;
    }
}

// ---------------- causal softmax (in place, zero-fills masked region) ----
__global__ __launch_bounds__(256)
void softmax_causal(float* __restrict__ S)
{
    int bq = blockIdx.x;
    int b = bq >> 10, q = bq & 1023;
    float* row = S + ((size_t)b * LL + q) * LL;
    int len = q + 1;
    int tid = threadIdx.x;
    __shared__ float red[256];

    float mx = -1e30f;
    for (int k = tid; k < len; k += 256) mx = fmaxf(mx, row[k]);
    red[tid] = mx; __syncthreads();
    for (int s = 128; s > 0; s >>= 1) {
        if (tid < s) red[tid] = fmaxf(red[tid], red[tid + s]);
        __syncthreads();
    }
    mx = red[0]; __syncthreads();

    float sum = 0.f;
    for (int k = tid; k < len; k += 256) sum += expf(row[k] - mx);
    red[tid] = sum; __syncthreads();
    for (int s = 128; s > 0; s >>= 1) {
        if (tid < s) red[tid] += red[tid + s];
        __syncthreads();
    }
    sum = red[0]; __syncthreads();

    float inv = 1.f / sum;
    for (int k = tid; k < LL; k += 256)
        row[k] = (k < len) ? expf(row[k] - mx) * inv : 0.f;
}

// ---------------- concat [out | ctx] ----------------
__global__ void concat_kernel(const float* __restrict__ Yout, const float* __restrict__ ctx,
                              float* __restrict__ cat)
{
    int i = blockIdx.x * 256 + threadIdx.x;
    if (i >= MM * 2 * HH) return;
    int m = i / (2 * HH), j = i % (2 * HH);
    cat[i] = (j < HH) ? Yout[(size_t)m * HH + j] : ctx[(size_t)m * HH + j - HH];
}

// ---------------- host ----------------
extern "C" void kernel_launch(void* const* d_in, const int* in_sizes, int n_in,
                              void* d_out, int out_size)
{
    const int*   x       = (const int*)d_in[0];
    const float* context = (const float*)d_in[1];
    const float* h_in    = (const float*)d_in[2];
    const float* c_in    = (const float*)d_in[3];
    const float* emb     = (const float*)d_in[4];
    const float* ctx_W   = (const float*)d_in[5];
    const float* ctx_b   = (const float*)d_in[6];
    const float* Wih0    = (const float*)d_in[7];
    const float* WihR    = (const float*)d_in[8];
    const float* Whh     = (const float*)d_in[9];
    const float* bih     = (const float*)d_in[10];
    const float* bhh     = (const float*)d_in[11];
    const float* Wa      = (const float*)d_in[12];
    const float* comb_W  = (const float*)d_in[13];
    const float* comb_b  = (const float*)d_in[14];
    const float* fc_W    = (const float*)d_in[15];
    const float* fc_b    = (const float*)d_in[16];
    float* out = (float*)d_out;

    float *x0, *seqA, *seqB, *pre, *preT, *keys, *scores, *cat, *comb, *hT;
    unsigned* barCount;
    cudaGetSymbolAddress((void**)&x0,       g_x0);
    cudaGetSymbolAddress((void**)&seqA,     g_seqA);
    cudaGetSymbolAddress((void**)&seqB,     g_seqB);
    cudaGetSymbolAddress((void**)&pre,      g_pre);
    cudaGetSymbolAddress((void**)&preT,     g_preT);
    cudaGetSymbolAddress((void**)&keys,     g_keys);
    cudaGetSymbolAddress((void**)&scores,   g_scores);
    cudaGetSymbolAddress((void**)&cat,      g_cat);
    cudaGetSymbolAddress((void**)&comb,     g_comb);
    cudaGetSymbolAddress((void**)&hT,       g_hT);
    cudaGetSymbolAddress((void**)&barCount, g_barCount);

    const int logitsN = MM * NVOCAB;             // 3,276,800
    const bool wantState = (out_size >= logitsN + 2 * NLAYER * BB * HH);

    // 1) embedding + context projection -> x0 [M,256]
    embed_kernel<<<(MM * EMB + 255) / 256, 256>>>(x, emb, x0);
    gemm_tc<<<dim3(1, 256, 1), 256>>>(context, CTXIN, ctx_W, CTXIN, ctx_b, nullptr,
                                      x0 + EMB, 2 * EMB, MM, EMB, CTXIN,
                                      1.f, 0, 0, 0, 1, 0, 0, 0);

    // 2) LSTM layers
    for (int l = 0; l < NLAYER; l++) {
        const float* X   = (l == 0) ? x0 : ((l == 1) ? seqA : ((l == 2) ? seqB : seqA));
        int          Kl  = (l == 0) ? 2 * EMB : HH;
        float*       Y   = (l % 2 == 0) ? seqA : seqB;
        const float* Wih = (l == 0) ? Wih0 : (WihR + (size_t)(l - 1) * G4 * HH);

        gemm_tc<<<dim3(G4 / 128, MM / 128, 1), 256>>>(X, Kl, Wih, Kl,
                                                      bih + l * G4, bhh + l * G4,
                                                      pre, G4, MM, G4, Kl,
                                                      1.f, 0, 0, 0, 1, 0, 0, 0);
        transpose_pre<<<dim3(LL, G4 / 32), dim3(32, 32)>>>(pre, preT);

        cudaMemsetAsync(barCount, 0, sizeof(unsigned));
        const float* Whh_l = Whh + (size_t)l * G4 * HH;
        float* outh = wantState ? (out + logitsN + l * BB * HH) : nullptr;
        float* outc = wantState ? (out + logitsN + NLAYER * BB * HH + l * BB * HH) : nullptr;
        lstm_layer<<<128, 96>>>(preT, Whh_l,
                                h_in + l * BB * HH, c_in + l * BB * HH,
                                Y, hT, outh, outc, wantState ? 1 : 0);
    }
    float* Y3 = seqB;  // layer-3 output

    // 3) attention
    gemm_tc<<<dim3(HH / 128, MM / 128, 1), 256>>>(Y3, HH, Wa, HH, nullptr, nullptr,
                                                  keys, HH, MM, HH, HH,
                                                  1.f, 0, 0, 0, 1, 0, 0, 0);
    float invs = 1.f / sqrtf((float)HH);
    gemm_tc<<<dim3(8, 8, 32), 256>>>(Y3, HH, keys, HH, nullptr, nullptr,
                                     scores, LL, LL, LL, HH,
                                     invs, 0, 1, 0, 1,
                                     (size_t)LL * HH, (size_t)LL * HH, (size_t)LL * LL);
    softmax_causal<<<BB * LL, 256>>>(scores);
    // ctx = attn @ out (trans=0, causal-K truncation); reuse keys buffer
    gemm_tc<<<dim3(HH / 128, 8, 32), 256>>>(scores, LL, Y3, HH, nullptr, nullptr,
                                            keys, HH, LL, HH, LL,
                                            1.f, 0, 0, 1, 0,
                                            (size_t)LL * LL, (size_t)LL * HH, (size_t)LL * HH);

    // 4) combine + output head
    concat_kernel<<<(MM * 2 * HH + 255) / 256, 256>>>(Y3, keys, cat);
    gemm_tc<<<dim3(HH / 128, MM / 128, 1), 256>>>(cat, 2 * HH, comb_W, 2 * HH,
                                                  comb_b, nullptr, comb, HH,
                                                  MM, HH, 2 * HH,
                                                  1.f, 1, 0, 0, 1, 0, 0, 0);
    gemm_tc<<<dim3(1, MM / 128, 1), 256>>>(comb, HH, fc_W, HH, fc_b, nullptr,
                                           out, NVOCAB, MM, NVOCAB, HH,
                                           1.f, 0, 0, 0, 1, 0, 0, 0);
}

// round 7
// speedup vs baseline: 1.4878x; 1.4674x over previous
#include <cuda_runtime.h>
#include <math.h>

// Problem constants
#define BB 32
#define LL 1024
#define EMB 128
#define HH 384
#define NLAYER 4
#define NVOCAB 100
#define G4 (4*HH)          // 1536
#define MM (BB*LL)         // 32768
#define CTXIN 300
#define HB (HH*BB)         // 12288
#define NCTA 96            // persistent LSTM CTAs

// ---------------- static scratch (no allocations allowed) ----------------
__device__ float g_x0[MM * 2 * EMB];            // layer-0 input [M,256]
__device__ float g_seqA[MM * HH];
__device__ float g_seqB[MM * HH];
__device__ float g_pre[(size_t)MM * G4];        // input projection [m=b*L+t][1536]
__device__ float g_preT[(size_t)MM * G4];       // transposed [t][row][b]
__device__ float g_keys[MM * HH];               // keys, later reused as ctx_vec
__device__ float g_scores[(size_t)BB * LL * LL];// attention scores / attn (in place)
__device__ float g_cat[MM * 2 * HH];            // [out | ctx]
__device__ float g_comb[MM * HH];
__device__ float g_hT[2 * HB];                  // double-buffered h, [k][b] layout
__device__ unsigned g_barCount;                 // grid barrier arrival counter

// ---------------- f32x2 packed-FMA helpers (PTX-only on sm_103a) ---------
__device__ __forceinline__ void fma2(unsigned long long& acc,
                                     unsigned long long a, unsigned long long b) {
    asm("fma.rn.f32x2 %0, %1, %2, %0;" : "+l"(acc) : "l"(a), "l"(b));
}
__device__ __forceinline__ unsigned long long pack2(float x, float y) {
    unsigned long long r;
    asm("mov.b64 %0, {%1, %2};" : "=l"(r) : "f"(x), "f"(y));
    return r;
}
__device__ __forceinline__ void unpack2(unsigned long long v, float& x, float& y) {
    asm("mov.b64 {%0, %1}, %2;" : "=f"(x), "=f"(y) : "l"(v));
}

// ---------------- tf32 helpers ----------------
__device__ __forceinline__ unsigned f2tf(float x) {
    unsigned r;
    asm("cvt.rna.tf32.f32 %0, %1;" : "=r"(r) : "f"(x));
    return r;
}

__device__ __forceinline__ void mma8(float* c, const unsigned* a, const unsigned* b) {
    asm volatile(
        "mma.sync.aligned.m16n8k8.row.col.f32.tf32.tf32.f32 "
        "{%0,%1,%2,%3}, {%4,%5,%6,%7}, {%8,%9}, {%0,%1,%2,%3};"
        : "+f"(c[0]), "+f"(c[1]), "+f"(c[2]), "+f"(c[3])
        : "r"(a[0]), "r"(a[1]), "r"(a[2]), "r"(a[3]), "r"(b[0]), "r"(b[1]));
}

// ---------------- tensor-core GEMM (3xTF32, ~fp32 accuracy) ----------------
// C = act(scale * (A @ OP) + b1 + b2)
//   trans=1: OP = W^T, W[N,K] row-major.  trans=0: OP = B, B[K,N] row-major.
#define SP 132
__global__ __launch_bounds__(256)
void gemm_tc(const float* __restrict__ A, int lda,
             const float* __restrict__ W, int ldw,
             const float* __restrict__ b1, const float* __restrict__ b2,
             float* __restrict__ C, int ldc,
             int M, int N, int K,
             float scale, int act, int causal, int causalK, int trans,
             size_t sA, size_t sW, size_t sC)
{
    int m0 = blockIdx.y * 128;
    int n0 = blockIdx.x * 128;
    if (causal && n0 > m0 + 127) return;
    A += (size_t)blockIdx.z * sA;
    W += (size_t)blockIdx.z * sW;
    C += (size_t)blockIdx.z * sC;
    int Klim = causalK ? min(K, m0 + 128) : K;

    __shared__ float As_hi[16 * SP], As_lo[16 * SP];
    __shared__ float Bs_hi[16 * SP], Bs_lo[16 * SP];

    const int tid = threadIdx.x;
    const int lr = tid >> 1, lq = tid & 1;
    const int kr = tid >> 4, nc = (tid & 15) * 8;
    const int lane = tid & 31;
    const int g = lane >> 2, tg = lane & 3;
    const int wid = tid >> 5;
    const int mBase = (wid & 3) * 32;
    const int nBase = (wid >> 2) * 64;

    float acc[2][8][4];
#pragma unroll
    for (int mt = 0; mt < 2; mt++)
#pragma unroll
        for (int nt = 0; nt < 8; nt++)
#pragma unroll
            for (int i = 0; i < 4; i++) acc[mt][nt][i] = 0.f;

    float4 a4[2], b4[2];

#define LOAD_TILE(K0)                                                          \
    {                                                                          \
        int k0_ = (K0);                                                        \
        const float* ap = A + (size_t)(m0 + lr) * lda;                         \
        _Pragma("unroll")                                                      \
        for (int j = 0; j < 2; j++) {                                          \
            int kb = k0_ + lq * 8 + j * 4;                                     \
            float4 v = make_float4(0.f, 0.f, 0.f, 0.f);                        \
            if (kb + 3 < Klim) v = *(const float4*)(ap + kb);                  \
            else {                                                             \
                if (kb + 0 < Klim) v.x = ap[kb + 0];                           \
                if (kb + 1 < Klim) v.y = ap[kb + 1];                           \
                if (kb + 2 < Klim) v.z = ap[kb + 2];                           \
            }                                                                  \
            a4[j] = v;                                                         \
        }                                                                      \
        if (trans) {                                                           \
            int wr = n0 + lr;                                                  \
            const float* wp = W + (size_t)wr * ldw;                            \
            _Pragma("unroll")                                                  \
            for (int j = 0; j < 2; j++) {                                      \
                int kb = k0_ + lq * 8 + j * 4;                                 \
                float4 v = make_float4(0.f, 0.f, 0.f, 0.f);                    \
                if (wr < N) {                                                  \
                    if (kb + 3 < Klim) v = *(const float4*)(wp + kb);          \
                    else {                                                     \
                        if (kb + 0 < Klim) v.x = wp[kb + 0];                   \
                        if (kb + 1 < Klim) v.y = wp[kb + 1];                   \
                        if (kb + 2 < Klim) v.z = wp[kb + 2];                   \
                    }                                                          \
                }                                                              \
                b4[j] = v;                                                     \
            }                                                                  \
        } else {                                                               \
            int kk = k0_ + kr;                                                 \
            _Pragma("unroll")                                                  \
            for (int j = 0; j < 2; j++) {                                      \
                float4 v = make_float4(0.f, 0.f, 0.f, 0.f);                    \
                if (kk < Klim)                                                 \
                    v = *(const float4*)(W + (size_t)kk * ldw + n0 + nc + j * 4);\
                b4[j] = v;                                                     \
            }                                                                  \
        }                                                                      \
    }

    LOAD_TILE(0);

    for (int k0 = 0; k0 < Klim; k0 += 16) {
#pragma unroll
        for (int j = 0; j < 2; j++) {
            const float* pv = &a4[j].x;
            int kb = lq * 8 + j * 4;
#pragma unroll
            for (int i = 0; i < 4; i++) {
                float a = pv[i];
                float hf = __uint_as_float(f2tf(a));
                As_hi[(kb + i) * SP + lr] = hf;
                As_lo[(kb + i) * SP + lr] = __uint_as_float(f2tf(a - hf));
            }
        }
        if (trans) {
#pragma unroll
            for (int j = 0; j < 2; j++) {
                const float* pv = &b4[j].x;
                int kb = lq * 8 + j * 4;
#pragma unroll
                for (int i = 0; i < 4; i++) {
                    float a = pv[i];
                    float hf = __uint_as_float(f2tf(a));
                    Bs_hi[(kb + i) * SP + lr] = hf;
                    Bs_lo[(kb + i) * SP + lr] = __uint_as_float(f2tf(a - hf));
                }
            }
        } else {
#pragma unroll
            for (int j = 0; j < 2; j++) {
                const float* pv = &b4[j].x;
#pragma unroll
                for (int i = 0; i < 4; i++) {
                    float a = pv[i];
                    float hf = __uint_as_float(f2tf(a));
                    Bs_hi[kr * SP + nc + j * 4 + i] = hf;
                    Bs_lo[kr * SP + nc + j * 4 + i] = __uint_as_float(f2tf(a - hf));
                }
            }
        }
        __syncthreads();

        if (k0 + 16 < Klim) LOAD_TILE(k0 + 16);

#pragma unroll
        for (int kt = 0; kt < 2; kt++) {
            int kr0 = kt * 8 + tg, kr1 = kt * 8 + tg + 4;
            unsigned ah[2][4], al[2][4];
#pragma unroll
            for (int mt = 0; mt < 2; mt++) {
                int m = mBase + mt * 16 + g;
                ah[mt][0] = __float_as_uint(As_hi[kr0 * SP + m]);
                ah[mt][1] = __float_as_uint(As_hi[kr0 * SP + m + 8]);
                ah[mt][2] = __float_as_uint(As_hi[kr1 * SP + m]);
                ah[mt][3] = __float_as_uint(As_hi[kr1 * SP + m + 8]);
                al[mt][0] = __float_as_uint(As_lo[kr0 * SP + m]);
                al[mt][1] = __float_as_uint(As_lo[kr0 * SP + m + 8]);
                al[mt][2] = __float_as_uint(As_lo[kr1 * SP + m]);
                al[mt][3] = __float_as_uint(As_lo[kr1 * SP + m + 8]);
            }
#pragma unroll
            for (int nt = 0; nt < 8; nt++) {
                int n = nBase + nt * 8 + g;
                unsigned bh[2], bl[2];
                bh[0] = __float_as_uint(Bs_hi[kr0 * SP + n]);
                bh[1] = __float_as_uint(Bs_hi[kr1 * SP + n]);
                bl[0] = __float_as_uint(Bs_lo[kr0 * SP + n]);
                bl[1] = __float_as_uint(Bs_lo[kr1 * SP + n]);
#pragma unroll
                for (int mt = 0; mt < 2; mt++) {
                    mma8(acc[mt][nt], ah[mt], bh);
                    mma8(acc[mt][nt], ah[mt], bl);
                    mma8(acc[mt][nt], al[mt], bh);
                }
            }
        }
        __syncthreads();
    }

#pragma unroll
    for (int mt = 0; mt < 2; mt++) {
        int row0 = m0 + mBase + mt * 16 + g;
        int row1 = row0 + 8;
#pragma unroll
        for (int nt = 0; nt < 8; nt++) {
            int col = n0 + nBase + nt * 8 + 2 * tg;
            float bias = 0.f;
            float bias1 = 0.f;
            if (col < N) {
                if (b1) bias += b1[col];
                if (b2) bias += b2[col];
            }
            if (col + 1 < N) {
                if (b1) bias1 += b1[col + 1];
                if (b2) bias1 += b2[col + 1];
            }
            float v0 = acc[mt][nt][0] * scale + bias;
            float v1 = acc[mt][nt][1] * scale + bias1;
            float v2 = acc[mt][nt][2] * scale + bias;
            float v3 = acc[mt][nt][3] * scale + bias1;
            if (act) { v0 = tanhf(v0); v1 = tanhf(v1); v2 = tanhf(v2); v3 = tanhf(v3); }
            if (col + 1 < N) {
                *(float2*)(C + (size_t)row0 * ldc + col) = make_float2(v0, v1);
                *(float2*)(C + (size_t)row1 * ldc + col) = make_float2(v2, v3);
            } else if (col < N) {
                C[(size_t)row0 * ldc + col] = v0;
                C[(size_t)row1 * ldc + col] = v2;
            }
        }
    }
}

// ---------------- embedding gather ----------------
__global__ void embed_kernel(const int* __restrict__ x, const float* __restrict__ emb,
                             float* __restrict__ X0)
{
    int i = blockIdx.x * 256 + threadIdx.x;
    if (i >= MM * EMB) return;
    int m = i >> 7, e = i & 127;
    X0[(size_t)m * 256 + e] = emb[(size_t)x[m] * EMB + e];
}

// ---------------- pre transpose: [b*L+t][row] -> [t][row][b] ------------
__global__ __launch_bounds__(1024)
void transpose_pre(const float* __restrict__ in, float* __restrict__ out)
{
    __shared__ float tile[32][33];
    int t = blockIdx.x;
    int r0 = blockIdx.y * 32;
    int x = threadIdx.x, y = threadIdx.y;
    tile[y][x] = in[((size_t)y * LL + t) * G4 + r0 + x];
    __syncthreads();
    out[((size_t)t * G4 + r0 + y) * BB + x] = tile[x][y];
}

// ---------------- persistent LSTM layer ----------------
// 96 CTAs x 128 threads (4 hidden dims x 32 batch per CTA), 1 warp/SMSP.
// Weights in SMEM (immune to the per-step L1 flush from __threadfence),
// f32x2 packed FMA (2 gates per instruction), pre prefetched under barrier.
__global__ __launch_bounds__(128, 1)
void lstm_layer(const float* __restrict__ preT,  // [t][row][b]
                const float* __restrict__ Whh,   // [1536,384]
                const float* __restrict__ h0,    // [B,H]
                const float* __restrict__ c0,    // [B,H]
                float* __restrict__ Y,           // [B,L,H]
                float* __restrict__ hT,          // [2][H][B]
                float* __restrict__ outh,        // [B,H] or null
                float* __restrict__ outc,
                int writeState)
{
    extern __shared__ float sm[];
    float* hs = sm;                         // 12288 floats (48 KB), [k][b]
    float2* smA = (float2*)(sm + HB);       // 4*384 float2: {Wi,Wf} pairs
    float2* smB = smA + 4 * HH;             // 4*384 float2: {Wg,Wo} pairs

    const int tid = threadIdx.x;
    const int b = tid & 31;
    const int jl = tid >> 5;
    const int jg = blockIdx.x * 4 + jl;

    // stage interleaved weights into smem (once)
    {
        const float* w0 = Whh + (size_t)jg * HH;
        const float* w1 = w0 + (size_t)HH * HH;
        const float* w2 = w1 + (size_t)HH * HH;
        const float* w3 = w2 + (size_t)HH * HH;
        for (int k = b; k < HH; k += 32) {
            smA[jl * HH + k] = make_float2(w0[k], w1[k]);
            smB[jl * HH + k] = make_float2(w2[k], w3[k]);
        }
    }

    float h = h0[b * HH + jg];
    float c = c0[b * HH + jg];
    hT[jg * BB + b] = h;       // buffer 0

    const float2* wa = smA + jl * HH;
    const float2* wb = smB + jl * HH;
    const int yb = blockIdx.x / 3;                 // Y-writer slice: batch
    const int ykc = (blockIdx.x % 3) * 128 + tid;  // Y-writer slice: hidden dim

    for (int t = 0; t < LL; t++) {
        // prefetch pre(t) into registers (completes during barrier wait;
        // registers are immune to the L1 flush below)
        size_t base = ((size_t)t * G4) * BB + b;
        float p0 = __ldcg(&preT[base + (size_t)jg * BB]);
        float p1 = __ldcg(&preT[base + (size_t)(HH + jg) * BB]);
        float p2 = __ldcg(&preT[base + (size_t)(2 * HH + jg) * BB]);
        float p3 = __ldcg(&preT[base + (size_t)(3 * HH + jg) * BB]);

        // ---- grid barrier #(t+1) ----
        __threadfence();
        __syncthreads();
        if (tid == 0) {
            atomicAdd(&g_barCount, 1u);
            unsigned tgt = (unsigned)NCTA * (unsigned)(t + 1);
            while (*((volatile unsigned*)&g_barCount) < tgt) {}
        }
        __syncthreads();

        // ---- stage h(t-1) into smem ----
        const float4* src = (const float4*)(hT + (t & 1) * HB);
        float4* dst4 = (float4*)hs;
#pragma unroll
        for (int i = 0; i < 24; i++)
            dst4[tid + i * 128] = __ldcv(src + tid + i * 128);
        __syncthreads();

        // coalesced Y[t-1] write from staged full-h (disjoint CTA slices)
        if (t > 0)
            Y[((size_t)yb * LL + (t - 1)) * HH + ykc] = hs[ykc * BB + yb];

        // ---- gates: packed {i,f} and {g,o} accumulation ----
        unsigned long long acc01 = pack2(p0, p1);
        unsigned long long acc23 = pack2(p2, p3);
#pragma unroll 8
        for (int k = 0; k < HH; k += 4) {
            unsigned long long a0 = *(const unsigned long long*)(wa + k);
            unsigned long long a1 = *(const unsigned long long*)(wa + k + 1);
            unsigned long long a2 = *(const unsigned long long*)(wa + k + 2);
            unsigned long long a3 = *(const unsigned long long*)(wa + k + 3);
            unsigned long long e0 = *(const unsigned long long*)(wb + k);
            unsigned long long e1 = *(const unsigned long long*)(wb + k + 1);
            unsigned long long e2 = *(const unsigned long long*)(wb + k + 2);
            unsigned long long e3 = *(const unsigned long long*)(wb + k + 3);
            float h0v = hs[(k + 0) * BB + b];
            float h1v = hs[(k + 1) * BB + b];
            float h2v = hs[(k + 2) * BB + b];
            float h3v = hs[(k + 3) * BB + b];
            unsigned long long hh0 = pack2(h0v, h0v);
            unsigned long long hh1 = pack2(h1v, h1v);
            unsigned long long hh2 = pack2(h2v, h2v);
            unsigned long long hh3 = pack2(h3v, h3v);
            fma2(acc01, a0, hh0); fma2(acc23, e0, hh0);
            fma2(acc01, a1, hh1); fma2(acc23, e1, hh1);
            fma2(acc01, a2, hh2); fma2(acc23, e2, hh2);
            fma2(acc01, a3, hh3); fma2(acc23, e3, hh3);
        }
        float g0, g1, g2, g3;
        unpack2(acc01, g0, g1);
        unpack2(acc23, g2, g3);

        float ig = 1.f / (1.f + expf(-g0));
        float fg = 1.f / (1.f + expf(-g1));
        float gg = tanhf(g2);
        float og = 1.f / (1.f + expf(-g3));
        c = fg * c + ig * gg;
        h = og * tanhf(c);

        hT[((t + 1) & 1) * HB + jg * BB + b] = h;
    }

    // tail: Y[L-1] (one scattered store per thread, once)
    Y[((size_t)b * LL + (LL - 1)) * HH + jg] = h;

    if (writeState) {
        outh[b * HH + jg] = h;
        outc[b * HH + jg] = c;
    }
}

// ---------------- causal softmax (in place, zero-fills masked region) ----
__global__ __launch_bounds__(256)
void softmax_causal(float* __restrict__ S)
{
    int bq = blockIdx.x;
    int b = bq >> 10, q = bq & 1023;
    float* row = S + ((size_t)b * LL + q) * LL;
    int len = q + 1;
    int tid = threadIdx.x;
    __shared__ float red[256];

    float mx = -1e30f;
    for (int k = tid; k < len; k += 256) mx = fmaxf(mx, row[k]);
    red[tid] = mx; __syncthreads();
    for (int s = 128; s > 0; s >>= 1) {
        if (tid < s) red[tid] = fmaxf(red[tid], red[tid + s]);
        __syncthreads();
    }
    mx = red[0]; __syncthreads();

    float sum = 0.f;
    for (int k = tid; k < len; k += 256) sum += expf(row[k] - mx);
    red[tid] = sum; __syncthreads();
    for (int s = 128; s > 0; s >>= 1) {
        if (tid < s) red[tid] += red[tid + s];
        __syncthreads();
    }
    sum = red[0]; __syncthreads();

    float inv = 1.f / sum;
    for (int k = tid; k < LL; k += 256)
        row[k] = (k < len) ? expf(row[k] - mx) * inv : 0.f;
}

// ---------------- concat [out | ctx] ----------------
__global__ void concat_kernel(const float* __restrict__ Yout, const float* __restrict__ ctx,
                              float* __restrict__ cat)
{
    int i = blockIdx.x * 256 + threadIdx.x;
    if (i >= MM * 2 * HH) return;
    int m = i / (2 * HH), j = i % (2 * HH);
    cat[i] = (j < HH) ? Yout[(size_t)m * HH + j] : ctx[(size_t)m * HH + j - HH];
}

// ---------------- host ----------------
extern "C" void kernel_launch(void* const* d_in, const int* in_sizes, int n_in,
                              void* d_out, int out_size)
{
    const int*   x       = (const int*)d_in[0];
    const float* context = (const float*)d_in[1];
    const float* h_in    = (const float*)d_in[2];
    const float* c_in    = (const float*)d_in[3];
    const float* emb     = (const float*)d_in[4];
    const float* ctx_W   = (const float*)d_in[5];
    const float* ctx_b   = (const float*)d_in[6];
    const float* Wih0    = (const float*)d_in[7];
    const float* WihR    = (const float*)d_in[8];
    const float* Whh     = (const float*)d_in[9];
    const float* bih     = (const float*)d_in[10];
    const float* bhh     = (const float*)d_in[11];
    const float* Wa      = (const float*)d_in[12];
    const float* comb_W  = (const float*)d_in[13];
    const float* comb_b  = (const float*)d_in[14];
    const float* fc_W    = (const float*)d_in[15];
    const float* fc_b    = (const float*)d_in[16];
    float* out = (float*)d_out;

    float *x0, *seqA, *seqB, *pre, *preT, *keys, *scores, *cat, *comb, *hT;
    unsigned* barCount;
    cudaGetSymbolAddress((void**)&x0,       g_x0);
    cudaGetSymbolAddress((void**)&seqA,     g_seqA);
    cudaGetSymbolAddress((void**)&seqB,     g_seqB);
    cudaGetSymbolAddress((void**)&pre,      g_pre);
    cudaGetSymbolAddress((void**)&preT,     g_preT);
    cudaGetSymbolAddress((void**)&keys,     g_keys);
    cudaGetSymbolAddress((void**)&scores,   g_scores);
    cudaGetSymbolAddress((void**)&cat,      g_cat);
    cudaGetSymbolAddress((void**)&comb,     g_comb);
    cudaGetSymbolAddress((void**)&hT,       g_hT);
    cudaGetSymbolAddress((void**)&barCount, g_barCount);

    const int lstmSmem = HB * 4 + 2 * 4 * HH * 8;   // 48KB h + 24KB weights = 73728
    cudaFuncSetAttribute(lstm_layer, cudaFuncAttributeMaxDynamicSharedMemorySize, lstmSmem);

    const int logitsN = MM * NVOCAB;             // 3,276,800
    const bool wantState = (out_size >= logitsN + 2 * NLAYER * BB * HH);

    // 1) embedding + context projection -> x0 [M,256]
    embed_kernel<<<(MM * EMB + 255) / 256, 256>>>(x, emb, x0);
    gemm_tc<<<dim3(1, 256, 1), 256>>>(context, CTXIN, ctx_W, CTXIN, ctx_b, nullptr,
                                      x0 + EMB, 2 * EMB, MM, EMB, CTXIN,
                                      1.f, 0, 0, 0, 1, 0, 0, 0);

    // 2) LSTM layers
    for (int l = 0; l < NLAYER; l++) {
        const float* X   = (l == 0) ? x0 : ((l == 1) ? seqA : ((l == 2) ? seqB : seqA));
        int          Kl  = (l == 0) ? 2 * EMB : HH;
        float*       Y   = (l % 2 == 0) ? seqA : seqB;
        const float* Wih = (l == 0) ? Wih0 : (WihR + (size_t)(l - 1) * G4 * HH);

        gemm_tc<<<dim3(G4 / 128, MM / 128, 1), 256>>>(X, Kl, Wih, Kl,
                                                      bih + l * G4, bhh + l * G4,
                                                      pre, G4, MM, G4, Kl,
                                                      1.f, 0, 0, 0, 1, 0, 0, 0);
        transpose_pre<<<dim3(LL, G4 / 32), dim3(32, 32)>>>(pre, preT);

        cudaMemsetAsync(barCount, 0, sizeof(unsigned));
        const float* Whh_l = Whh + (size_t)l * G4 * HH;
        float* outh = wantState ? (out + logitsN + l * BB * HH) : nullptr;
        float* outc = wantState ? (out + logitsN + NLAYER * BB * HH + l * BB * HH) : nullptr;
        lstm_layer<<<NCTA, 128, lstmSmem>>>(preT, Whh_l,
                                            h_in + l * BB * HH, c_in + l * BB * HH,
                                            Y, hT, outh, outc, wantState ? 1 : 0);
    }
    float* Y3 = seqB;  // layer-3 output

    // 3) attention
    gemm_tc<<<dim3(HH / 128, MM / 128, 1), 256>>>(Y3, HH, Wa, HH, nullptr, nullptr,
                                                  keys, HH, MM, HH, HH,
                                                  1.f, 0, 0, 0, 1, 0, 0, 0);
    float invs = 1.f / sqrtf((float)HH);
    gemm_tc<<<dim3(8, 8, 32), 256>>>(Y3, HH, keys, HH, nullptr, nullptr,
                                     scores, LL, LL, LL, HH,
                                     invs, 0, 1, 0, 1,
                                     (size_t)LL * HH, (size_t)LL * HH, (size_t)LL * LL);
    softmax_causal<<<BB * LL, 256>>>(scores);
    gemm_tc<<<dim3(HH / 128, 8, 32), 256>>>(scores, LL, Y3, HH, nullptr, nullptr,
                                            keys, HH, LL, HH, LL,
                                            1.f, 0, 0, 1, 0,
                                            (size_t)LL * LL, (size_t)LL * HH, (size_t)LL * HH);

    // 4) combine + output head
    concat_kernel<<<(MM * 2 * HH + 255) / 256, 256>>>(Y3, keys, cat);
    gemm_tc<<<dim3(HH / 128, MM / 128, 1), 256>>>(cat, 2 * HH, comb_W, 2 * HH,
                                                  comb_b, nullptr, comb, HH,
                                                  MM, HH, 2 * HH,
                                                  1.f, 1, 0, 0, 1, 0, 0, 0);
    gemm_tc<<<dim3(1, MM / 128, 1), 256>>>(comb, HH, fc_W, HH, fc_b, nullptr,
                                           out, NVOCAB, MM, NVOCAB, HH,
                                           1.f, 0, 0, 0, 1, 0, 0, 0);
}